// round 1
// baseline (speedup 1.0000x reference)
#include <cuda_runtime.h>
#include <math.h>

#define BATCH 4
#define SEQ   4096
#define DIM   1024
#define NK    64

// Scratch (device globals — no allocation allowed)
__device__ float g_aff[BATCH * SEQ * NK];   // 4 MB
__device__ float g_agg[BATCH * NK * DIM];   // 1 MB
__device__ float g_ss [BATCH * NK * DIM];   // 1 MB
__device__ float g_m2 [BATCH * NK * DIM];   // 1 MB
__device__ float g_c2 [NK];
__device__ float g_inv[NK];

// ---------------------------------------------------------------------------
// centers prep: c2[k] = |c_k|^2 ; inv[k] = -0.5 / clip(exp(ls),0.1,2)^2
// ---------------------------------------------------------------------------
__global__ void centers_prep(const float* __restrict__ centers,
                             const float* __restrict__ ls) {
    int c = blockIdx.x;
    int tid = threadIdx.x;
    float p = 0.f;
    for (int d = tid; d < DIM; d += 128) {
        float v = centers[c * DIM + d];
        p += v * v;
    }
    __shared__ float red[128];
    red[tid] = p;
    __syncthreads();
    for (int off = 64; off; off >>= 1) {
        if (tid < off) red[tid] += red[tid + off];
        __syncthreads();
    }
    if (tid == 0) {
        g_c2[c] = red[0];
        float s = expf(ls[c]);
        s = fminf(fmaxf(s, 0.1f), 2.0f);
        g_inv[c] = -0.5f / (s * s);
    }
}

// ---------------------------------------------------------------------------
// affinity: per 64-token tile, compute xc = X @ C^T (64x64, K-loop 1024),
// fuse |x|^2, d2 = max(x2 - 2xc + c2, 0), aff = exp(inv*d2), row-normalize.
// ---------------------------------------------------------------------------
__global__ void affinity_kernel(const float* __restrict__ x,
                                const float* __restrict__ centers) {
    __shared__ float Xs[16][65];
    __shared__ float Cs[16][65];
    __shared__ float x2s[64];
    __shared__ float sOut[64][65];
    __shared__ float sC2[NK], sInv[NK];

    int tid = threadIdx.x;              // 256 threads
    int t0  = blockIdx.x * 64;          // global token tile
    if (tid < 64) {
        x2s[tid] = 0.f;
        sC2[tid] = g_c2[tid];
        sInv[tid] = g_inv[tid];
    }
    int tx = tid & 15, ty = tid >> 4;   // 16x16 thread grid, 4x4 micro-tile
    int lr = tid >> 2, lc = (tid & 3) << 2;

    float acc[4][4];
#pragma unroll
    for (int i = 0; i < 4; i++)
#pragma unroll
        for (int j = 0; j < 4; j++) acc[i][j] = 0.f;

    const float4* xg = (const float4*)(x + (size_t)(t0 + lr) * DIM + lc);
    const float4* cg = (const float4*)(centers + (size_t)lr * DIM + lc);

    __syncthreads();
    for (int kk = 0; kk < DIM; kk += 16) {
        float4 xv = xg[kk >> 2];
        float4 cv = cg[kk >> 2];
        __syncthreads();
        Xs[lc + 0][lr] = xv.x; Xs[lc + 1][lr] = xv.y;
        Xs[lc + 2][lr] = xv.z; Xs[lc + 3][lr] = xv.w;
        Cs[lc + 0][lr] = cv.x; Cs[lc + 1][lr] = cv.y;
        Cs[lc + 2][lr] = cv.z; Cs[lc + 3][lr] = cv.w;
        atomicAdd(&x2s[lr], xv.x * xv.x + xv.y * xv.y + xv.z * xv.z + xv.w * xv.w);
        __syncthreads();
#pragma unroll
        for (int k = 0; k < 16; k++) {
            float a0 = Xs[k][ty], a1 = Xs[k][ty + 16],
                  a2 = Xs[k][ty + 32], a3 = Xs[k][ty + 48];
            float b0 = Cs[k][tx], b1 = Cs[k][tx + 16],
                  b2 = Cs[k][tx + 32], b3 = Cs[k][tx + 48];
            acc[0][0] += a0 * b0; acc[0][1] += a0 * b1; acc[0][2] += a0 * b2; acc[0][3] += a0 * b3;
            acc[1][0] += a1 * b0; acc[1][1] += a1 * b1; acc[1][2] += a1 * b2; acc[1][3] += a1 * b3;
            acc[2][0] += a2 * b0; acc[2][1] += a2 * b1; acc[2][2] += a2 * b2; acc[2][3] += a2 * b3;
            acc[3][0] += a3 * b0; acc[3][1] += a3 * b1; acc[3][2] += a3 * b2; acc[3][3] += a3 * b3;
        }
    }
    __syncthreads();
#pragma unroll
    for (int i = 0; i < 4; i++)
#pragma unroll
        for (int j = 0; j < 4; j++)
            sOut[ty + 16 * i][tx + 16 * j] = acc[i][j];
    __syncthreads();

    if (tid < 64) {
        float x2 = x2s[tid];
        float sum = 0.f;
#pragma unroll 8
        for (int k = 0; k < NK; k++) {
            float d2 = fmaxf(x2 - 2.f * sOut[tid][k] + sC2[k], 0.f);
            float v = expf(sInv[k] * d2);
            sOut[tid][k] = v;
            sum += v;
        }
        x2s[tid] = 1.f / (sum + 1e-8f);
    }
    __syncthreads();
    // coalesced writeout of normalized affinities
    for (int idx = tid; idx < 64 * 64; idx += 256) {
        int r = idx >> 6, c = idx & 63;
        g_aff[(size_t)(t0 + r) * NK + c] = sOut[r][c] * x2s[r];
    }
}

// ---------------------------------------------------------------------------
// aggregate: agg[b,k,d] += sum_{s in chunk} aff[b,s,k] * x[b,s,d]
// grid (DIM/128, SEQ/256, BATCH), split-S via fp32 atomics.
// ---------------------------------------------------------------------------
__global__ void aggregate_kernel(const float* __restrict__ x) {
    int b  = blockIdx.z;
    int d0 = blockIdx.x * 128;
    int s0 = blockIdx.y * 256;
    __shared__ float As[16][65];    // [s][k]
    __shared__ float Bs[16][129];   // [s][d]

    int tid = threadIdx.x;          // 256
    int tx = tid & 31, ty = tid >> 5;   // k = ty+8i (i<8), d = tx+32j (j<4)
    int ra = tid >> 4, ca = (tid & 15) << 2;
    int rb = tid >> 5, cb = (tid & 31) << 2;

    float acc[8][4];
#pragma unroll
    for (int i = 0; i < 8; i++)
#pragma unroll
        for (int j = 0; j < 4; j++) acc[i][j] = 0.f;

    for (int ss = 0; ss < 256; ss += 16) {
        int s = s0 + ss;
        float4 av = *(const float4*)&g_aff[(size_t)(b * SEQ + s + ra) * NK + ca];
        float4 b0 = *(const float4*)&x[(size_t)(b * SEQ + s + rb) * DIM + d0 + cb];
        float4 b1 = *(const float4*)&x[(size_t)(b * SEQ + s + rb + 8) * DIM + d0 + cb];
        __syncthreads();
        As[ra][ca + 0] = av.x; As[ra][ca + 1] = av.y;
        As[ra][ca + 2] = av.z; As[ra][ca + 3] = av.w;
        Bs[rb][cb + 0] = b0.x; Bs[rb][cb + 1] = b0.y;
        Bs[rb][cb + 2] = b0.z; Bs[rb][cb + 3] = b0.w;
        Bs[rb + 8][cb + 0] = b1.x; Bs[rb + 8][cb + 1] = b1.y;
        Bs[rb + 8][cb + 2] = b1.z; Bs[rb + 8][cb + 3] = b1.w;
        __syncthreads();
#pragma unroll
        for (int s2 = 0; s2 < 16; s2++) {
            float a[8], bb[4];
#pragma unroll
            for (int i = 0; i < 8; i++) a[i] = As[s2][ty + 8 * i];
#pragma unroll
            for (int j = 0; j < 4; j++) bb[j] = Bs[s2][tx + 32 * j];
#pragma unroll
            for (int i = 0; i < 8; i++)
#pragma unroll
                for (int j = 0; j < 4; j++) acc[i][j] += a[i] * bb[j];
        }
    }
#pragma unroll
    for (int i = 0; i < 8; i++)
#pragma unroll
        for (int j = 0; j < 4; j++)
            atomicAdd(&g_agg[(size_t)(b * NK + ty + 8 * i) * DIM + d0 + tx + 32 * j],
                      acc[i][j]);
}

// ---------------------------------------------------------------------------
// small NT GEMM with split-D: C[m,n] += sum_{d in chunk} A[m,d] * W[n,d]
// M = BATCH*NK = 256, N = DIM. grid (M/64, DIM/64, 4).
// ---------------------------------------------------------------------------
__global__ void gemm_nt_split(const float* __restrict__ A,
                              const float* __restrict__ W,
                              float* __restrict__ C) {
    int m0 = blockIdx.x * 64, n0 = blockIdx.y * 64, d0 = blockIdx.z * 256;
    __shared__ float Xs[16][65];
    __shared__ float Ws[16][65];
    int tid = threadIdx.x;
    int tx = tid & 15, ty = tid >> 4;
    int lr = tid >> 2, lc = (tid & 3) << 2;

    float acc[4][4];
#pragma unroll
    for (int i = 0; i < 4; i++)
#pragma unroll
        for (int j = 0; j < 4; j++) acc[i][j] = 0.f;

    for (int kk = d0; kk < d0 + 256; kk += 16) {
        float4 av = *(const float4*)&A[(size_t)(m0 + lr) * DIM + kk + lc];
        float4 wv = *(const float4*)&W[(size_t)(n0 + lr) * DIM + kk + lc];
        __syncthreads();
        Xs[lc + 0][lr] = av.x; Xs[lc + 1][lr] = av.y;
        Xs[lc + 2][lr] = av.z; Xs[lc + 3][lr] = av.w;
        Ws[lc + 0][lr] = wv.x; Ws[lc + 1][lr] = wv.y;
        Ws[lc + 2][lr] = wv.z; Ws[lc + 3][lr] = wv.w;
        __syncthreads();
#pragma unroll
        for (int k = 0; k < 16; k++) {
            float a0 = Xs[k][ty], a1 = Xs[k][ty + 16],
                  a2 = Xs[k][ty + 32], a3 = Xs[k][ty + 48];
            float b0 = Ws[k][tx], b1 = Ws[k][tx + 16],
                  b2 = Ws[k][tx + 32], b3 = Ws[k][tx + 48];
            acc[0][0] += a0 * b0; acc[0][1] += a0 * b1; acc[0][2] += a0 * b2; acc[0][3] += a0 * b3;
            acc[1][0] += a1 * b0; acc[1][1] += a1 * b1; acc[1][2] += a1 * b2; acc[1][3] += a1 * b3;
            acc[2][0] += a2 * b0; acc[2][1] += a2 * b1; acc[2][2] += a2 * b2; acc[2][3] += a2 * b3;
            acc[3][0] += a3 * b0; acc[3][1] += a3 * b1; acc[3][2] += a3 * b2; acc[3][3] += a3 * b3;
        }
    }
#pragma unroll
    for (int i = 0; i < 4; i++)
#pragma unroll
        for (int j = 0; j < 4; j++)
            atomicAdd(&C[(size_t)(m0 + ty + 16 * i) * DIM + n0 + tx + 16 * j],
                      acc[i][j]);
}

// ---------------------------------------------------------------------------
// distribute: out[b,s,e] = sum_k aff[b,s,k] * m2[b,k,e]
// grid (DIM/128, SEQ/64, BATCH); 64 tokens x 128 e per block, k in 2 chunks.
// ---------------------------------------------------------------------------
__global__ void distribute_kernel(float* __restrict__ out) {
    int b = blockIdx.z, e0 = blockIdx.x * 128, s0 = blockIdx.y * 64;
    __shared__ float sA[64][33];    // [token][k-chunk 32]
    __shared__ float sB[32][129];   // [k][e]
    int tid = threadIdx.x;
    int tx = tid & 31, ty = tid >> 5;   // t = ty+8i (i<8), e = tx+32j (j<4)

    float acc[8][4];
#pragma unroll
    for (int i = 0; i < 8; i++)
#pragma unroll
        for (int j = 0; j < 4; j++) acc[i][j] = 0.f;

    for (int kk = 0; kk < NK; kk += 32) {
        __syncthreads();
        {
            int f = tid, r = f >> 3, c = (f & 7) << 2;
            float4 v = *(const float4*)&g_aff[(size_t)(b * SEQ + s0 + r) * NK + kk + c];
            sA[r][c + 0] = v.x; sA[r][c + 1] = v.y; sA[r][c + 2] = v.z; sA[r][c + 3] = v.w;
            f = tid + 256; r = f >> 3; c = (f & 7) << 2;
            v = *(const float4*)&g_aff[(size_t)(b * SEQ + s0 + r) * NK + kk + c];
            sA[r][c + 0] = v.x; sA[r][c + 1] = v.y; sA[r][c + 2] = v.z; sA[r][c + 3] = v.w;
        }
#pragma unroll
        for (int q = 0; q < 4; q++) {
            int f = tid + q * 256, r = f >> 5, c = (f & 31) << 2;
            float4 v = *(const float4*)&g_m2[(size_t)(b * NK + kk + r) * DIM + e0 + c];
            sB[r][c + 0] = v.x; sB[r][c + 1] = v.y; sB[r][c + 2] = v.z; sB[r][c + 3] = v.w;
        }
        __syncthreads();
#pragma unroll
        for (int k = 0; k < 32; k++) {
            float a[8], bb[4];
#pragma unroll
            for (int i = 0; i < 8; i++) a[i] = sA[ty + 8 * i][k];
#pragma unroll
            for (int j = 0; j < 4; j++) bb[j] = sB[k][tx + 32 * j];
#pragma unroll
            for (int i = 0; i < 8; i++)
#pragma unroll
                for (int j = 0; j < 4; j++) acc[i][j] += a[i] * bb[j];
        }
    }
#pragma unroll
    for (int i = 0; i < 8; i++)
#pragma unroll
        for (int j = 0; j < 4; j++)
            out[(size_t)(b * SEQ + s0 + ty + 8 * i) * DIM + e0 + tx + 32 * j] = acc[i][j];
}

// ---------------------------------------------------------------------------
extern "C" void kernel_launch(void* const* d_in, const int* in_sizes, int n_in,
                              void* d_out, int out_size) {
    const float* x       = (const float*)d_in[0];  // [4,4096,1024]
    const float* centers = (const float*)d_in[1];  // [64,1024]
    const float* ls      = (const float*)d_in[2];  // [64]
    const float* Wv      = (const float*)d_in[3];  // [1024,1024]
    const float* Wo      = (const float*)d_in[4];  // [1024,1024]
    float* out = (float*)d_out;

    void *p_agg, *p_ss, *p_m2;
    cudaGetSymbolAddress(&p_agg, g_agg);
    cudaGetSymbolAddress(&p_ss,  g_ss);
    cudaGetSymbolAddress(&p_m2,  g_m2);

    centers_prep<<<NK, 128>>>(centers, ls);
    affinity_kernel<<<(BATCH * SEQ) / 64, 256>>>(x, centers);

    cudaMemsetAsync(p_agg, 0, sizeof(float) * BATCH * NK * DIM);
    aggregate_kernel<<<dim3(DIM / 128, SEQ / 256, BATCH), 256>>>(x);

    cudaMemsetAsync(p_ss, 0, sizeof(float) * BATCH * NK * DIM);
    gemm_nt_split<<<dim3(BATCH * NK / 64, DIM / 64, 4), 256>>>((const float*)p_agg, Wv, (float*)p_ss);

    cudaMemsetAsync(p_m2, 0, sizeof(float) * BATCH * NK * DIM);
    gemm_nt_split<<<dim3(BATCH * NK / 64, DIM / 64, 4), 256>>>((const float*)p_ss, Wo, (float*)p_m2);

    distribute_kernel<<<dim3(DIM / 128, SEQ / 64, BATCH), 256>>>(out);
}